// round 13
// baseline (speedup 1.0000x reference)
#include <cuda_runtime.h>
#include <cuda_bf16.h>

// ConvKB scoring, f32x2-packed version.
//   score[e] = sum_{c,d} relu(w0_c*h[row,d] + w1_c*h[col,d] + w2_c*g[t,d] + cb_c) * lw[c,d] + lb
// E=50000, D=128, C=32.
//
// Warp processes EB=4 edges per batch; lane owns d = 4*lane..4*lane+3 (two f32x2).
// Outer loop over channels c: conv params (broadcast) + lw[c] loaded from shared
// once per c, amortized over 4 edges. Math in packed fma.rn.f32x2.

#define D 128
#define C 32
#define EB 4
#define WARPS_PER_BLOCK 8
#define THREADS (WARPS_PER_BLOCK * 32)

typedef unsigned long long ull;

__device__ __forceinline__ ull pack2(float lo, float hi) {
    ull r; asm("mov.b64 %0,{%1,%2};" : "=l"(r) : "f"(lo), "f"(hi)); return r;
}
__device__ __forceinline__ float2 unpack2(ull x) {
    float2 f; asm("mov.b64 {%0,%1},%2;" : "=f"(f.x), "=f"(f.y) : "l"(x)); return f;
}
__device__ __forceinline__ ull fma2(ull a, ull b, ull c) {
    ull d; asm("fma.rn.f32x2 %0,%1,%2,%3;" : "=l"(d) : "l"(a), "l"(b), "l"(c)); return d;
}
__device__ __forceinline__ ull relu2(ull x) {
    asm("{\n\t"
        ".reg .f32 lo, hi;\n\t"
        "mov.b64 {lo,hi}, %0;\n\t"
        "max.f32 lo, lo, 0f00000000;\n\t"
        "max.f32 hi, hi, 0f00000000;\n\t"
        "mov.b64 %0, {lo,hi};\n\t"
        "}" : "+l"(x));
    return x;
}

__global__ void __launch_bounds__(THREADS) convkb_kernel(
    const float* __restrict__ h,
    const float* __restrict__ g,
    const int*   __restrict__ edge_idx,   // [2, E] int32
    const int*   __restrict__ edge_type,  // [E]    int32
    const float* __restrict__ conv_w,     // [C,3]
    const float* __restrict__ conv_b,     // [C]
    const float* __restrict__ lin_w,      // [C*D]
    const float* __restrict__ lin_b,      // [1]
    float* __restrict__ out,              // [E]
    int n_edges)
{
    __shared__ float4 s_lin[C * D / 4];   // [c][lane] float4 = 16 KB
    __shared__ ull    s_convp[C * 4];     // per c: {w0,w0},{w1,w1},{w2,w2},{b,b} = 1 KB

    const int tid = threadIdx.x;

    const float4* lw4 = reinterpret_cast<const float4*>(lin_w);
    #pragma unroll 4
    for (int i = tid; i < C * D / 4; i += THREADS) s_lin[i] = lw4[i];
    if (tid < C) {
        float w0 = conv_w[tid * 3 + 0];
        float w1 = conv_w[tid * 3 + 1];
        float w2 = conv_w[tid * 3 + 2];
        float cb = conv_b[tid];
        s_convp[tid * 4 + 0] = pack2(w0, w0);
        s_convp[tid * 4 + 1] = pack2(w1, w1);
        s_convp[tid * 4 + 2] = pack2(w2, w2);
        s_convp[tid * 4 + 3] = pack2(cb, cb);
    }
    __syncthreads();

    const float bias_out = lin_b[0];

    const unsigned s_lin_base  = (unsigned)__cvta_generic_to_shared(s_lin);
    const unsigned s_conv_base = (unsigned)__cvta_generic_to_shared(s_convp);

    const int warp = tid >> 5;
    const int lane = tid & 31;
    const int warp_global = blockIdx.x * WARPS_PER_BLOCK + warp;
    const int n_warps = gridDim.x * WARPS_PER_BLOCK;

    for (int e0 = warp_global * EB; e0 < n_edges; e0 += n_warps * EB) {
        // --- gather indices for 4 edges (clamped; broadcast L1-hit loads) ---
        int row[EB], col[EB], typ[EB];
        #pragma unroll
        for (int k = 0; k < EB; k++) {
            int e = e0 + k; if (e >= n_edges) e = n_edges - 1;
            row[k] = edge_idx[e];
            col[k] = edge_idx[n_edges + e];
            typ[k] = edge_type[e];
        }

        // --- load embeddings: lane's float4 as two packed f32x2 ---
        ull a[EB][2], b[EB][2], r[EB][2];
        #pragma unroll
        for (int k = 0; k < EB; k++) {
            ulonglong2 va = reinterpret_cast<const ulonglong2*>(h + (size_t)row[k] * D)[lane];
            ulonglong2 vb = reinterpret_cast<const ulonglong2*>(h + (size_t)col[k] * D)[lane];
            ulonglong2 vr = reinterpret_cast<const ulonglong2*>(g + (size_t)typ[k] * D)[lane];
            a[k][0] = va.x; a[k][1] = va.y;
            b[k][0] = vb.x; b[k][1] = vb.y;
            r[k][0] = vr.x; r[k][1] = vr.y;
        }

        ull acc[EB][2];
        #pragma unroll
        for (int k = 0; k < EB; k++) { acc[k][0] = 0ULL; acc[k][1] = 0ULL; }

        // --- channel loop: conv params + lw loaded once per c, used for 4 edges ---
        #pragma unroll 8
        for (int c = 0; c < C; c++) {
            ull w00, w11, w22, bb, lw0, lw1;
            unsigned ca = s_conv_base + c * 32;
            asm("ld.shared.v2.u64 {%0,%1},[%2];" : "=l"(w00), "=l"(w11) : "r"(ca));
            asm("ld.shared.v2.u64 {%0,%1},[%2];" : "=l"(w22), "=l"(bb)  : "r"(ca + 16));
            unsigned la = s_lin_base + (unsigned)(c * 32 + lane) * 16;
            asm("ld.shared.v2.u64 {%0,%1},[%2];" : "=l"(lw0), "=l"(lw1) : "r"(la));

            #pragma unroll
            for (int k = 0; k < EB; k++) {
                ull t0 = fma2(w22, r[k][0], bb);
                ull t1 = fma2(w22, r[k][1], bb);
                t0 = fma2(w11, b[k][0], t0);
                t1 = fma2(w11, b[k][1], t1);
                t0 = fma2(w00, a[k][0], t0);
                t1 = fma2(w00, a[k][1], t1);
                t0 = relu2(t0);
                t1 = relu2(t1);
                acc[k][0] = fma2(t0, lw0, acc[k][0]);
                acc[k][1] = fma2(t1, lw1, acc[k][1]);
            }
        }

        // --- per-edge reduction over lanes + halves ---
        #pragma unroll
        for (int k = 0; k < EB; k++) {
            float2 u0 = unpack2(acc[k][0]);
            float2 u1 = unpack2(acc[k][1]);
            float s = (u0.x + u0.y) + (u1.x + u1.y);
            #pragma unroll
            for (int o = 16; o > 0; o >>= 1)
                s += __shfl_xor_sync(0xFFFFFFFFu, s, o);
            if (lane == 0 && (e0 + k) < n_edges)
                out[e0 + k] = s + bias_out;
        }
    }
}

extern "C" void kernel_launch(void* const* d_in, const int* in_sizes, int n_in,
                              void* d_out, int out_size) {
    const float* h         = (const float*)d_in[0];
    const float* g         = (const float*)d_in[1];
    const int*   edge_idx  = (const int*)d_in[2];
    const int*   edge_type = (const int*)d_in[3];
    const float* conv_w    = (const float*)d_in[4];
    const float* conv_b    = (const float*)d_in[5];
    const float* lin_w     = (const float*)d_in[6];
    const float* lin_b     = (const float*)d_in[7];
    float*       out       = (float*)d_out;

    const int n_edges = in_sizes[3];  // edge_type element count == E

    // One EB-batch per warp: ceil(E / (EB * warps_per_block)) blocks.
    int nblocks = (n_edges + EB * WARPS_PER_BLOCK - 1) / (EB * WARPS_PER_BLOCK);

    convkb_kernel<<<nblocks, THREADS>>>(h, g, edge_idx, edge_type,
                                        conv_w, conv_b, lin_w, lin_b,
                                        out, n_edges);
}

// round 14
// speedup vs baseline: 1.6022x; 1.6022x over previous
#include <cuda_runtime.h>
#include <cuda_bf16.h>

// ConvKB scoring, f32x2-packed, EB=2, occupancy-fixed.
//   score[e] = sum_{c,d} relu(w0_c*h[row,d] + w1_c*h[col,d] + w2_c*g[t,d] + cb_c) * lw[c,d] + lb
// E=50000, D=128, C=32.
//
// Warp processes EB=2 edges per iteration of a grid-stride loop; lane owns
// d = 4*lane..4*lane+3 (two f32x2). Channel-outer loop amortizes conv/lin
// weight LDS over both edges. __launch_bounds__(256,4) caps regs at 64 so
// 4 CTAs/SM stay resident (R13 failed at 94 regs / 2 CTAs / 23% occ).

#define D 128
#define C 32
#define EB 2
#define WARPS_PER_BLOCK 8
#define THREADS (WARPS_PER_BLOCK * 32)
#define NBLOCKS (148 * 4)   // 4 CTAs/SM, grid-stride

typedef unsigned long long ull;

__device__ __forceinline__ ull pack2(float lo, float hi) {
    ull r; asm("mov.b64 %0,{%1,%2};" : "=l"(r) : "f"(lo), "f"(hi)); return r;
}
__device__ __forceinline__ float2 unpack2(ull x) {
    float2 f; asm("mov.b64 {%0,%1},%2;" : "=f"(f.x), "=f"(f.y) : "l"(x)); return f;
}
__device__ __forceinline__ ull fma2(ull a, ull b, ull c) {
    ull d; asm("fma.rn.f32x2 %0,%1,%2,%3;" : "=l"(d) : "l"(a), "l"(b), "l"(c)); return d;
}
__device__ __forceinline__ ull relu2(ull x) {
    asm("{\n\t"
        ".reg .f32 lo, hi;\n\t"
        "mov.b64 {lo,hi}, %0;\n\t"
        "max.f32 lo, lo, 0f00000000;\n\t"
        "max.f32 hi, hi, 0f00000000;\n\t"
        "mov.b64 %0, {lo,hi};\n\t"
        "}" : "+l"(x));
    return x;
}

__global__ void __launch_bounds__(THREADS, 4) convkb_kernel(
    const float* __restrict__ h,
    const float* __restrict__ g,
    const int*   __restrict__ edge_idx,   // [2, E] int32
    const int*   __restrict__ edge_type,  // [E]    int32
    const float* __restrict__ conv_w,     // [C,3]
    const float* __restrict__ conv_b,     // [C]
    const float* __restrict__ lin_w,      // [C*D]
    const float* __restrict__ lin_b,      // [1]
    float* __restrict__ out,              // [E]
    int n_edges)
{
    __shared__ float4 s_lin[C * D / 4];   // [c][lane] float4 = 16 KB
    __shared__ ull    s_convp[C * 4];     // per c: {w0,w0},{w1,w1},{w2,w2},{b,b}

    const int tid = threadIdx.x;

    const float4* lw4 = reinterpret_cast<const float4*>(lin_w);
    #pragma unroll 4
    for (int i = tid; i < C * D / 4; i += THREADS) s_lin[i] = lw4[i];
    if (tid < C) {
        float w0 = conv_w[tid * 3 + 0];
        float w1 = conv_w[tid * 3 + 1];
        float w2 = conv_w[tid * 3 + 2];
        float cb = conv_b[tid];
        s_convp[tid * 4 + 0] = pack2(w0, w0);
        s_convp[tid * 4 + 1] = pack2(w1, w1);
        s_convp[tid * 4 + 2] = pack2(w2, w2);
        s_convp[tid * 4 + 3] = pack2(cb, cb);
    }
    __syncthreads();

    const float bias_out = lin_b[0];

    const unsigned s_lin_base  = (unsigned)__cvta_generic_to_shared(s_lin);
    const unsigned s_conv_base = (unsigned)__cvta_generic_to_shared(s_convp);

    const int warp = tid >> 5;
    const int lane = tid & 31;
    const int warp_global = blockIdx.x * WARPS_PER_BLOCK + warp;
    const int n_warps = gridDim.x * WARPS_PER_BLOCK;

    for (int e0 = warp_global * EB; e0 < n_edges; e0 += n_warps * EB) {
        // --- indices for 2 edges (clamped; broadcast L1-hit loads) ---
        int row[EB], col[EB], typ[EB];
        #pragma unroll
        for (int k = 0; k < EB; k++) {
            int e = e0 + k; if (e >= n_edges) e = n_edges - 1;
            row[k] = edge_idx[e];
            col[k] = edge_idx[n_edges + e];
            typ[k] = edge_type[e];
        }

        // --- embeddings: lane's float4 as two packed f32x2 ---
        ull a[EB][2], b[EB][2], r[EB][2];
        #pragma unroll
        for (int k = 0; k < EB; k++) {
            ulonglong2 va = reinterpret_cast<const ulonglong2*>(h + (size_t)row[k] * D)[lane];
            ulonglong2 vb = reinterpret_cast<const ulonglong2*>(h + (size_t)col[k] * D)[lane];
            ulonglong2 vr = reinterpret_cast<const ulonglong2*>(g + (size_t)typ[k] * D)[lane];
            a[k][0] = va.x; a[k][1] = va.y;
            b[k][0] = vb.x; b[k][1] = vb.y;
            r[k][0] = vr.x; r[k][1] = vr.y;
        }

        ull acc[EB][2];
        #pragma unroll
        for (int k = 0; k < EB; k++) { acc[k][0] = 0ULL; acc[k][1] = 0ULL; }

        // --- channel loop: weights loaded once per c, used for both edges ---
        #pragma unroll 4
        for (int c = 0; c < C; c++) {
            ull w00, w11, w22, bb, lw0, lw1;
            unsigned ca = s_conv_base + c * 32;
            asm("ld.shared.v2.u64 {%0,%1},[%2];" : "=l"(w00), "=l"(w11) : "r"(ca));
            asm("ld.shared.v2.u64 {%0,%1},[%2];" : "=l"(w22), "=l"(bb)  : "r"(ca + 16));
            unsigned la = s_lin_base + (unsigned)(c * 32 + lane) * 16;
            asm("ld.shared.v2.u64 {%0,%1},[%2];" : "=l"(lw0), "=l"(lw1) : "r"(la));

            #pragma unroll
            for (int k = 0; k < EB; k++) {
                ull t0 = fma2(w22, r[k][0], bb);
                ull t1 = fma2(w22, r[k][1], bb);
                t0 = fma2(w11, b[k][0], t0);
                t1 = fma2(w11, b[k][1], t1);
                t0 = fma2(w00, a[k][0], t0);
                t1 = fma2(w00, a[k][1], t1);
                t0 = relu2(t0);
                t1 = relu2(t1);
                acc[k][0] = fma2(t0, lw0, acc[k][0]);
                acc[k][1] = fma2(t1, lw1, acc[k][1]);
            }
        }

        // --- per-edge reduction over halves + lanes ---
        #pragma unroll
        for (int k = 0; k < EB; k++) {
            float2 u0 = unpack2(acc[k][0]);
            float2 u1 = unpack2(acc[k][1]);
            float s = (u0.x + u0.y) + (u1.x + u1.y);
            #pragma unroll
            for (int o = 16; o > 0; o >>= 1)
                s += __shfl_xor_sync(0xFFFFFFFFu, s, o);
            if (lane == 0 && (e0 + k) < n_edges)
                out[e0 + k] = s + bias_out;
        }
    }
}

extern "C" void kernel_launch(void* const* d_in, const int* in_sizes, int n_in,
                              void* d_out, int out_size) {
    const float* h         = (const float*)d_in[0];
    const float* g         = (const float*)d_in[1];
    const int*   edge_idx  = (const int*)d_in[2];
    const int*   edge_type = (const int*)d_in[3];
    const float* conv_w    = (const float*)d_in[4];
    const float* conv_b    = (const float*)d_in[5];
    const float* lin_w     = (const float*)d_in[6];
    const float* lin_b     = (const float*)d_in[7];
    float*       out       = (float*)d_out;

    const int n_edges = in_sizes[3];  // edge_type element count == E

    int nblocks = NBLOCKS;
    int max_needed = (n_edges + EB * WARPS_PER_BLOCK - 1) / (EB * WARPS_PER_BLOCK);
    if (nblocks > max_needed) nblocks = max_needed;

    convkb_kernel<<<nblocks, THREADS>>>(h, g, edge_idx, edge_type,
                                        conv_w, conv_b, lin_w, lin_b,
                                        out, n_edges);
}